// round 8
// baseline (speedup 1.0000x reference)
#include <cuda_runtime.h>
#include <cstdint>
#include <cstddef>

#define N_TOK   131072
#define DIM     64
#define KCODES  1024
#define CHUNK   64          // codes per smem chunk (raw floats: 64*64*4 = 16KB)
#define NCHUNKS (KCODES / CHUNK)
#define ABLK    128         // argmin CTA threads (= tokens per CTA)
#define QBLOCKS 512         // quantize kernel blocks (256 tokens each)

// Output layout (float32, flattened tuple order):
//   [0]                      loss
//   [1 .. 1+N*D)             quantized_st
//   [1+N*D]                  perplexity
//   [2+N*D .. 2+N*D+N)       encoding_indices (as float)
#define OUT_Q    ((size_t)1)
#define OUT_PERP ((size_t)1 + (size_t)N_TOK * DIM)
#define OUT_IDX  ((size_t)2 + (size_t)N_TOK * DIM)

typedef unsigned long long u64;

// ---------------- device scratch (no allocations allowed) ----------------
__device__ float  g_e2[KCODES];
__device__ int    g_idx[N_TOK];
__device__ int    g_counts[KCODES];
__device__ double g_block_sse[QBLOCKS];

// ---------------- packed f32x2 helpers (FFMA2 path, sm_103a) -------------
__device__ __forceinline__ void ffma2(u64& d, u64 a, u64 b) {
    asm("fma.rn.f32x2 %0, %1, %2, %0;" : "+l"(d) : "l"(a), "l"(b));
}
__device__ __forceinline__ float2 unpack2(u64 v) {
    float2 f; asm("mov.b64 {%0, %1}, %2;" : "=f"(f.x), "=f"(f.y) : "l"(v)); return f;
}

// ---------------- cp.async helpers ---------------------------------------
__device__ __forceinline__ void cp_async16(void* smem_dst, const void* gsrc) {
    uint32_t s = (uint32_t)__cvta_generic_to_shared(smem_dst);
    asm volatile("cp.async.cg.shared.global [%0], [%1], 16;" :: "r"(s), "l"(gsrc));
}
__device__ __forceinline__ void cp_commit() {
    asm volatile("cp.async.commit_group;");
}
template <int N>
__device__ __forceinline__ void cp_wait() {
    asm volatile("cp.async.wait_group %0;" :: "n"(N));
}

// ---------------- kernel 0: prep (e2 per code, zero counts) --------------
__global__ void vq_prep_kernel(const float* __restrict__ cb) {
    int k = blockIdx.x * blockDim.x + threadIdx.x;
    if (k < KCODES) {
        const float* row = cb + (size_t)k * DIM;
        float s0 = 0.f, s1 = 0.f, s2 = 0.f, s3 = 0.f;
        #pragma unroll
        for (int i = 0; i < DIM; i += 4) {
            s0 = fmaf(row[i+0], row[i+0], s0);
            s1 = fmaf(row[i+1], row[i+1], s1);
            s2 = fmaf(row[i+2], row[i+2], s2);
            s3 = fmaf(row[i+3], row[i+3], s3);
        }
        g_e2[k] = (s0 + s1) + (s2 + s3);
        g_counts[k] = 0;
    }
}

// ---------------- kernel 1: argmin (the hot GEMM-like kernel) ------------
// 1024 CTAs x 128 threads, occ 6 (888 slots -> thin 136-CTA tail wave).
// ONE token per thread; FROZEN per-token arithmetic (identical to R4/R6):
//   x2  : single packed chain over all dims, then lane.x + lane.y
//   dot : single packed chain a += px[2i]*v.x; a += px[2i+1]*v.y
//   d   = fmaf(dot, -2, x2) + e2 ; strict '<' with ascending code index.
__global__ void __launch_bounds__(ABLK, 6)
vq_argmin_kernel(const float* __restrict__ x, const float* __restrict__ cb,
                 float* __restrict__ out_idx_f) {
    __shared__ __align__(16) float s_e[2][CHUNK * DIM];   // 2 x 16KB
    __shared__ float s_e2[KCODES];                        // 4KB

    const int tid = threadIdx.x;
    const int t   = blockIdx.x * ABLK + tid;              // token index

    // e2 table -> smem (once)
    #pragma unroll
    for (int i = 0; i < KCODES / ABLK; ++i)
        s_e2[i * ABLK + tid] = g_e2[i * ABLK + tid];

    // Load token row; consecutive-dim pairs are native f32x2 operands.
    u64 px[DIM / 2];
    {
        const ulonglong2* r = reinterpret_cast<const ulonglong2*>(x + (size_t)t * DIM);
        #pragma unroll
        for (int i = 0; i < DIM / 4; ++i) {
            ulonglong2 v = r[i];
            px[2*i]   = v.x;
            px[2*i+1] = v.y;
        }
    }

    // |x|^2 : single chain over all packed pairs (frozen order)
    float x2;
    {
        u64 qa = 0ull;
        #pragma unroll
        for (int j = 0; j < DIM / 2; ++j)
            ffma2(qa, px[j], px[j]);
        float2 f = unpack2(qa);
        x2 = f.x + f.y;
    }

    // Prefetch chunk 0 (16KB = 1024 x 16B; 8 per thread)
    const float4* csrc = reinterpret_cast<const float4*>(cb);
    {
        float4* dst = reinterpret_cast<float4*>(s_e[0]);
        #pragma unroll
        for (int j = 0; j < 8; ++j)
            cp_async16(dst + j * ABLK + tid, csrc + j * ABLK + tid);
        cp_commit();
    }

    float best = 3.4e38f;
    int   bi   = 0;
    int   buf  = 0;

    for (int cc = 0; cc < NCHUNKS; ++cc) {
        const int c0 = cc * CHUNK;
        if (cc < NCHUNKS - 1) {
            const float4* src = csrc + (size_t)(c0 + CHUNK) * (DIM / 4);
            float4* dst = reinterpret_cast<float4*>(s_e[buf ^ 1]);
            #pragma unroll
            for (int j = 0; j < 8; ++j)
                cp_async16(dst + j * ABLK + tid, src + j * ABLK + tid);
            cp_commit();
            cp_wait<1>();       // chunk cc has landed; cc+1 still in flight
        } else {
            cp_wait<0>();
        }
        __syncthreads();

        const float* sb = s_e[buf];
        #pragma unroll 2
        for (int k = 0; k < CHUNK; ++k) {
            const ulonglong2* e = reinterpret_cast<const ulonglong2*>(sb + k * DIM);
            u64 a = 0ull;             // SINGLE chain (frozen rounding order)
            #pragma unroll
            for (int i = 0; i < DIM / 4; ++i) {
                ulonglong2 v = e[i];              // broadcast LDS.128
                ffma2(a, px[2*i],   v.x);
                ffma2(a, px[2*i+1], v.y);
            }
            float2 f = unpack2(a);
            float dot = f.x + f.y;
            float d = fmaf(dot, -2.0f, x2) + s_e2[c0 + k];
            if (d < best) { best = d; bi = c0 + k; }
        }
        __syncthreads();        // all warps done with s_e[buf] before overwrite
        buf ^= 1;
    }

    g_idx[t] = bi;
    out_idx_f[t] = (float)bi;
}

// ---------------- kernel 2: quantize + MSE partials + histogram ----------
// 512 CTAs x 256 threads; each CTA handles 256 tokens.
// Thread = (token sub-slot, dim): tid = sub*64 + dim -> coalesced I/O.
// NOTE: output region starts at dout+1 (4B offset) -> stores MUST be scalar.
__global__ void __launch_bounds__(256)
vq_quantize_kernel(const float* __restrict__ x, const float* __restrict__ cb,
                   float* __restrict__ dout) {
    __shared__ int   sbins[KCODES];
    __shared__ float swarp[8];

    for (int i = threadIdx.x; i < KCODES; i += 256) sbins[i] = 0;
    __syncthreads();

    const int dim  = threadIdx.x & 63;
    const int sub  = threadIdx.x >> 6;     // 0..3
    const int base = blockIdx.x * 256;

    float lsum = 0.f;
    #pragma unroll 4
    for (int it = 0; it < 64; ++it) {
        int t   = base + it * 4 + sub;
        int idx = g_idx[t];
        float q  = cb[(size_t)idx * DIM + dim];
        float xv = x[(size_t)t * DIM + dim];
        float df = q - xv;                              // quantized - inputs
        dout[OUT_Q + (size_t)t * DIM + dim] = xv + df;  // straight-through value
        lsum = fmaf(df, df, lsum);
        if (dim == 0) atomicAdd(&sbins[idx], 1);
    }

    // block-reduce lsum (deterministic tree)
    #pragma unroll
    for (int o = 16; o > 0; o >>= 1) lsum += __shfl_down_sync(0xffffffffu, lsum, o);
    if ((threadIdx.x & 31) == 0) swarp[threadIdx.x >> 5] = lsum;
    __syncthreads();
    if (threadIdx.x == 0) {
        float s = 0.f;
        #pragma unroll
        for (int w = 0; w < 8; ++w) s += swarp[w];
        g_block_sse[blockIdx.x] = (double)s;
    }

    // merge histogram (integer atomics: exact + deterministic)
    for (int i = threadIdx.x; i < KCODES; i += 256) {
        int c = sbins[i];
        if (c) atomicAdd(&g_counts[i], c);
    }
}

// ---------------- kernel 3: finalize loss + perplexity -------------------
__global__ void vq_finalize_kernel(float* __restrict__ dout) {
    __shared__ double sd[256];
    const int tid = threadIdx.x;

    // deterministic sum of per-block SSE
    double s = 0.0;
    for (int i = tid; i < QBLOCKS; i += 256) s += g_block_sse[i];
    sd[tid] = s;
    __syncthreads();
    #pragma unroll
    for (int o = 128; o > 0; o >>= 1) {
        if (tid < o) sd[tid] += sd[tid + o];
        __syncthreads();
    }
    double sse = sd[0];
    __syncthreads();

    // entropy: H = sum p*log(p + 1e-10), p = counts / N
    double h = 0.0;
    for (int i = tid; i < KCODES; i += 256) {
        float p = (float)g_counts[i] * (1.0f / (float)N_TOK);
        h += (double)(p * logf(p + 1e-10f));
    }
    sd[tid] = h;
    __syncthreads();
    #pragma unroll
    for (int o = 128; o > 0; o >>= 1) {
        if (tid < o) sd[tid] += sd[tid + o];
        __syncthreads();
    }

    if (tid == 0) {
        float mse = (float)(sse / ((double)N_TOK * (double)DIM));
        dout[0]        = mse + 0.25f * mse;          // (1 + beta) * mse
        dout[OUT_PERP] = expf((float)(-sd[0]));      // exp(-sum p log p)
    }
}

// ---------------- launch ---------------------------------------------------
extern "C" void kernel_launch(void* const* d_in, const int* in_sizes, int n_in,
                              void* d_out, int out_size) {
    const float* x  = (const float*)d_in[0];
    const float* cb = (const float*)d_in[1];
    // defensive: metadata order is (inputs, codebook); swap if sizes disagree
    if (n_in >= 2 && in_sizes[0] == KCODES * DIM && in_sizes[1] == N_TOK * DIM) {
        const float* t = x; x = cb; cb = t;
    }
    float* out = (float*)d_out;

    vq_prep_kernel<<<(KCODES + 255) / 256, 256>>>(cb);
    vq_argmin_kernel<<<N_TOK / ABLK, ABLK>>>(x, cb, out + OUT_IDX);
    vq_quantize_kernel<<<QBLOCKS, 256>>>(x, cb, out);
    vq_finalize_kernel<<<1, 256>>>(out);
}

// round 9
// speedup vs baseline: 1.6777x; 1.6777x over previous
#include <cuda_runtime.h>
#include <cstdint>
#include <cstddef>

#define N_TOK   131072
#define DIM     64
#define KCODES  1024
#define KHALF   (KCODES / 2)     // codes per argmin CTA (code-split)
#define CHUNK   64               // codes per smem chunk (raw floats: 16KB)
#define NCHUNKS (KHALF / CHUNK)  // 8 chunks per half
#define ABLK    128              // argmin CTA threads
#define ATILE   (2 * ABLK)       // tokens per argmin CTA (T=2)
#define QBLOCKS 512              // quantize kernel blocks (256 tokens each)

// Output layout (float32, flattened tuple order):
//   [0]                      loss
//   [1 .. 1+N*D)             quantized_st
//   [1+N*D]                  perplexity
//   [2+N*D .. 2+N*D+N)       encoding_indices (as float)
#define OUT_Q    ((size_t)1)
#define OUT_PERP ((size_t)1 + (size_t)N_TOK * DIM)
#define OUT_IDX  ((size_t)2 + (size_t)N_TOK * DIM)

typedef unsigned long long u64;

// ---------------- device scratch (no allocations allowed) ----------------
__device__ float  g_e2[KCODES];
__device__ u64    g_key[N_TOK];      // (dist_bits << 32) | idx, merged by atomicMin
__device__ int    g_counts[KCODES];
__device__ double g_block_sse[QBLOCKS];

// ---------------- packed f32x2 helpers (FFMA2 path, sm_103a) -------------
__device__ __forceinline__ void ffma2(u64& d, u64 a, u64 b) {
    asm("fma.rn.f32x2 %0, %1, %2, %0;" : "+l"(d) : "l"(a), "l"(b));
}
__device__ __forceinline__ float2 unpack2(u64 v) {
    float2 f; asm("mov.b64 {%0, %1}, %2;" : "=f"(f.x), "=f"(f.y) : "l"(v)); return f;
}

// ---------------- cp.async helpers ---------------------------------------
__device__ __forceinline__ void cp_async16(void* smem_dst, const void* gsrc) {
    uint32_t s = (uint32_t)__cvta_generic_to_shared(smem_dst);
    asm volatile("cp.async.cg.shared.global [%0], [%1], 16;" :: "r"(s), "l"(gsrc));
}
__device__ __forceinline__ void cp_commit() {
    asm volatile("cp.async.commit_group;");
}
template <int N>
__device__ __forceinline__ void cp_wait() {
    asm volatile("cp.async.wait_group %0;" :: "n"(N));
}

// ---------------- kernel 0: prep (e2, zero counts, init keys) ------------
__global__ void vq_prep_kernel(const float* __restrict__ cb) {
    int i = blockIdx.x * blockDim.x + threadIdx.x;   // [0, N_TOK)
    if (i < KCODES) {
        const float* row = cb + (size_t)i * DIM;
        float s0 = 0.f, s1 = 0.f, s2 = 0.f, s3 = 0.f;
        #pragma unroll
        for (int j = 0; j < DIM; j += 4) {
            s0 = fmaf(row[j+0], row[j+0], s0);
            s1 = fmaf(row[j+1], row[j+1], s1);
            s2 = fmaf(row[j+2], row[j+2], s2);
            s3 = fmaf(row[j+3], row[j+3], s3);
        }
        g_e2[i] = (s0 + s1) + (s2 + s3);
        g_counts[i] = 0;
    }
    g_key[i] = 0xFFFFFFFFFFFFFFFFull;
}

// ---------------- kernel 1: argmin over a code-half -----------------------
// Grid 1024 = 512 token-tiles x 2 code-halves; 128 thr, T=2 tokens/thread,
// occ 3. FROZEN per-token arithmetic (identical to the 452us passing R4):
//   x2  : single packed chain over all dims, then lane.x + lane.y
//   dot : single packed chain a += px[2i]*v.x; a += px[2i+1]*v.y
//   d   = fmaf(dot, -2, x2) + e2 ; strict '<' with ascending code index.
// Halves merged exactly via atomicMin on (dist_bits, idx) keys.
__global__ void __launch_bounds__(ABLK, 3)
vq_argmin_kernel(const float* __restrict__ x, const float* __restrict__ cb) {
    __shared__ __align__(16) float s_e[2][CHUNK * DIM];   // 2 x 16KB
    __shared__ float s_e2[KHALF];                         // 2KB

    const int half  = blockIdx.x & 1;                 // code half
    const int tile  = blockIdx.x >> 1;                // token tile
    const int tid   = threadIdx.x;
    const int cbase = half * KHALF;
    const int t0    = tile * ATILE + 2 * tid;
    const int t1    = t0 + 1;

    // e2 slice for this half -> smem
    #pragma unroll
    for (int i = 0; i < KHALF / ABLK; ++i)
        s_e2[i * ABLK + tid] = g_e2[cbase + i * ABLK + tid];

    // Load 2 token rows; consecutive-dim pairs are native f32x2 operands.
    u64 px0[DIM / 2], px1[DIM / 2];
    {
        const ulonglong2* r0 = reinterpret_cast<const ulonglong2*>(x + (size_t)t0 * DIM);
        const ulonglong2* r1 = reinterpret_cast<const ulonglong2*>(x + (size_t)t1 * DIM);
        #pragma unroll
        for (int i = 0; i < DIM / 4; ++i) {
            ulonglong2 a = r0[i]; px0[2*i] = a.x; px0[2*i+1] = a.y;
            ulonglong2 b = r1[i]; px1[2*i] = b.x; px1[2*i+1] = b.y;
        }
    }

    // |x|^2 per token: single chain each (frozen order)
    float x20, x21;
    {
        u64 qa = 0ull, qb = 0ull;
        #pragma unroll
        for (int j = 0; j < DIM / 2; ++j) {
            ffma2(qa, px0[j], px0[j]);
            ffma2(qb, px1[j], px1[j]);
        }
        float2 fa = unpack2(qa), fb = unpack2(qb);
        x20 = fa.x + fa.y;
        x21 = fb.x + fb.y;
    }

    // Prefetch chunk 0 of this half (16KB; 8 x 16B per thread)
    const float4* csrc = reinterpret_cast<const float4*>(cb) + (size_t)cbase * (DIM / 4);
    {
        float4* dst = reinterpret_cast<float4*>(s_e[0]);
        #pragma unroll
        for (int j = 0; j < 8; ++j)
            cp_async16(dst + j * ABLK + tid, csrc + j * ABLK + tid);
        cp_commit();
    }

    float best0 = 3.4e38f, best1 = 3.4e38f;
    int   bi0 = 0, bi1 = 0;
    int   buf = 0;

    for (int cc = 0; cc < NCHUNKS; ++cc) {
        const int c0 = cc * CHUNK;                    // offset within half
        if (cc < NCHUNKS - 1) {
            const float4* src = csrc + (size_t)(c0 + CHUNK) * (DIM / 4);
            float4* dst = reinterpret_cast<float4*>(s_e[buf ^ 1]);
            #pragma unroll
            for (int j = 0; j < 8; ++j)
                cp_async16(dst + j * ABLK + tid, src + j * ABLK + tid);
            cp_commit();
            cp_wait<1>();       // chunk cc landed; cc+1 in flight
        } else {
            cp_wait<0>();
        }
        __syncthreads();

        const float* sb = s_e[buf];
        #pragma unroll 2
        for (int k = 0; k < CHUNK; ++k) {
            const ulonglong2* e = reinterpret_cast<const ulonglong2*>(sb + k * DIM);
            u64 a = 0ull, b = 0ull;   // one frozen chain per token
            #pragma unroll
            for (int i = 0; i < DIM / 4; ++i) {
                ulonglong2 v = e[i];              // broadcast LDS.128
                ffma2(a, px0[2*i],   v.x);
                ffma2(a, px0[2*i+1], v.y);
                ffma2(b, px1[2*i],   v.x);
                ffma2(b, px1[2*i+1], v.y);
            }
            float2 fa = unpack2(a), fb = unpack2(b);
            float dot0 = fa.x + fa.y;
            float dot1 = fb.x + fb.y;
            float e2 = s_e2[c0 + k];
            float d0 = fmaf(dot0, -2.0f, x20) + e2;
            float d1 = fmaf(dot1, -2.0f, x21) + e2;
            int kk = cbase + c0 + k;
            if (d0 < best0) { best0 = d0; bi0 = kk; }
            if (d1 < best1) { best1 = d1; bi1 = kk; }
        }
        __syncthreads();        // all warps done with s_e[buf] before overwrite
        buf ^= 1;
    }

    // Exact cross-half merge: distances here are ~|x|^2 (>0), so float bits
    // are order-preserving; key = (dist_bits, idx) -> min == (lowest dist,
    // lowest idx on tie) == reference argmin semantics.
    u64 k0 = ((u64)__float_as_uint(best0) << 32) | (unsigned)bi0;
    u64 k1 = ((u64)__float_as_uint(best1) << 32) | (unsigned)bi1;
    atomicMin(&g_key[t0], k0);
    atomicMin(&g_key[t1], k1);
}

// ---------------- kernel 2: quantize + MSE partials + histogram ----------
// 512 CTAs x 256 threads; each CTA handles 256 tokens.
// Thread = (token sub-slot, dim): tid = sub*64 + dim -> coalesced I/O.
// NOTE: output region starts at dout+1 (4B offset) -> stores MUST be scalar.
__global__ void __launch_bounds__(256)
vq_quantize_kernel(const float* __restrict__ x, const float* __restrict__ cb,
                   float* __restrict__ dout) {
    __shared__ int   sbins[KCODES];
    __shared__ float swarp[8];

    for (int i = threadIdx.x; i < KCODES; i += 256) sbins[i] = 0;
    __syncthreads();

    const int dim  = threadIdx.x & 63;
    const int sub  = threadIdx.x >> 6;     // 0..3
    const int base = blockIdx.x * 256;
    float* out_idx_f = dout + OUT_IDX;

    float lsum = 0.f;
    #pragma unroll 4
    for (int it = 0; it < 64; ++it) {
        int t   = base + it * 4 + sub;
        int idx = (int)(unsigned)g_key[t];              // low word = winner idx
        float q  = cb[(size_t)idx * DIM + dim];
        float xv = x[(size_t)t * DIM + dim];
        float df = q - xv;                              // quantized - inputs
        dout[OUT_Q + (size_t)t * DIM + dim] = xv + df;  // straight-through value
        lsum = fmaf(df, df, lsum);
        if (dim == 0) {
            atomicAdd(&sbins[idx], 1);
            out_idx_f[t] = (float)idx;
        }
    }

    // block-reduce lsum (deterministic tree)
    #pragma unroll
    for (int o = 16; o > 0; o >>= 1) lsum += __shfl_down_sync(0xffffffffu, lsum, o);
    if ((threadIdx.x & 31) == 0) swarp[threadIdx.x >> 5] = lsum;
    __syncthreads();
    if (threadIdx.x == 0) {
        float s = 0.f;
        #pragma unroll
        for (int w = 0; w < 8; ++w) s += swarp[w];
        g_block_sse[blockIdx.x] = (double)s;
    }

    // merge histogram (integer atomics: exact + deterministic)
    for (int i = threadIdx.x; i < KCODES; i += 256) {
        int c = sbins[i];
        if (c) atomicAdd(&g_counts[i], c);
    }
}

// ---------------- kernel 3: finalize loss + perplexity -------------------
__global__ void vq_finalize_kernel(float* __restrict__ dout) {
    __shared__ double sd[256];
    const int tid = threadIdx.x;

    // deterministic sum of per-block SSE
    double s = 0.0;
    for (int i = tid; i < QBLOCKS; i += 256) s += g_block_sse[i];
    sd[tid] = s;
    __syncthreads();
    #pragma unroll
    for (int o = 128; o > 0; o >>= 1) {
        if (tid < o) sd[tid] += sd[tid + o];
        __syncthreads();
    }
    double sse = sd[0];
    __syncthreads();

    // entropy: H = sum p*log(p + 1e-10), p = counts / N
    double h = 0.0;
    for (int i = tid; i < KCODES; i += 256) {
        float p = (float)g_counts[i] * (1.0f / (float)N_TOK);
        h += (double)(p * logf(p + 1e-10f));
    }
    sd[tid] = h;
    __syncthreads();
    #pragma unroll
    for (int o = 128; o > 0; o >>= 1) {
        if (tid < o) sd[tid] += sd[tid + o];
        __syncthreads();
    }

    if (tid == 0) {
        float mse = (float)(sse / ((double)N_TOK * (double)DIM));
        dout[0]        = mse + 0.25f * mse;          // (1 + beta) * mse
        dout[OUT_PERP] = expf((float)(-sd[0]));      // exp(-sum p log p)
    }
}

// ---------------- launch ---------------------------------------------------
extern "C" void kernel_launch(void* const* d_in, const int* in_sizes, int n_in,
                              void* d_out, int out_size) {
    const float* x  = (const float*)d_in[0];
    const float* cb = (const float*)d_in[1];
    // defensive: metadata order is (inputs, codebook); swap if sizes disagree
    if (n_in >= 2 && in_sizes[0] == KCODES * DIM && in_sizes[1] == N_TOK * DIM) {
        const float* t = x; x = cb; cb = t;
    }
    float* out = (float*)d_out;

    vq_prep_kernel<<<N_TOK / 256, 256>>>(cb);
    vq_argmin_kernel<<<(N_TOK / ATILE) * 2, ABLK>>>(x, cb);
    vq_quantize_kernel<<<QBLOCKS, 256>>>(x, cb, out);
    vq_finalize_kernel<<<1, 256>>>(out);
}